// round 1
// baseline (speedup 1.0000x reference)
#include <cuda_runtime.h>

#define LQ 512
#define LK 512
#define DD 256
#define HH1 256
#define HH2 128
#define BB 2

// scratch: transposed projections [b][h][q]
__device__ float g_qp[BB * HH1 * LQ];
__device__ float g_kp[BB * HH1 * LK];

// ---------- packed fp32x2 helpers ----------
__device__ __forceinline__ unsigned long long ffma2(unsigned long long a,
                                                    unsigned long long b,
                                                    unsigned long long c) {
    unsigned long long d;
    asm("fma.rn.f32x2 %0, %1, %2, %3;" : "=l"(d) : "l"(a), "l"(b), "l"(c));
    return d;
}
__device__ __forceinline__ unsigned long long dup2(float x) {
    unsigned long long d;
    unsigned int u = __float_as_uint(x);
    asm("mov.b64 %0, {%1, %1};" : "=l"(d) : "r"(u));
    return d;
}
__device__ __forceinline__ float2 unpk(unsigned long long v) {
    unsigned int lo, hi;
    asm("mov.b64 {%0, %1}, %2;" : "=r"(lo), "=r"(hi) : "l"(v));
    return make_float2(__uint_as_float(lo), __uint_as_float(hi));
}

// ---------------------------------------------------------------------------
// Kernel 1: projections.  qp[b][h][q] = sum_d query[b][q][d]*W1[d][h] + b1[h]
//           kp[b][h][k]   = sum_d key[b][k][d]*W1[D+d][h]
// blockIdx: (q-group of 8, b, which)   threads: 256 (= h)
// ---------------------------------------------------------------------------
__global__ void proj_kernel(const float* __restrict__ query,
                            const float* __restrict__ key,
                            const float* __restrict__ W1,
                            const float* __restrict__ b1) {
    const int h = threadIdx.x;         // 0..255
    const int q0 = blockIdx.x * 8;
    const int b = blockIdx.y;
    const int which = blockIdx.z;      // 0 -> query/qp, 1 -> key/kp

    const float* X = (which ? key : query) + ((long)b * LQ + q0) * DD;

    __shared__ float sx[8 * DD];
    #pragma unroll
    for (int i = threadIdx.x; i < 8 * DD; i += 256) sx[i] = X[i];
    __syncthreads();

    float acc[8];
    const float bias = which ? 0.f : b1[h];
    #pragma unroll
    for (int r = 0; r < 8; r++) acc[r] = bias;

    const float* Wcol = W1 + (long)(which * DD) * HH1 + h;
    #pragma unroll 4
    for (int d = 0; d < DD; d++) {
        float w = Wcol[(long)d * HH1];
        #pragma unroll
        for (int r = 0; r < 8; r++) acc[r] = fmaf(sx[r * DD + d], w, acc[r]);
    }

    float* dst = (which ? g_kp : g_qp) + (long)b * (HH1 * LQ) + (long)h * LQ + q0;
    #pragma unroll
    for (int r = 0; r < 8; r++) dst[r] = acc[r];
}

// ---------------------------------------------------------------------------
// Kernel 2: fused MLP scores.
// For each (q,k): h1[h]=relu(qp[q,h]+kp[k,h]); h2=relu(h1@W2+b2);
// score = h2@W3 + b3 -> written to scores[b][q][k] (attn region of d_out).
// Block: BQ=16 x BK=16 pairs, all 128 j.  256 threads:
//   jt = tid&7 (16 j each), kt = (tid>>3)&3 (4 k each), qt = tid>>5 (2 q each)
// ---------------------------------------------------------------------------
#define BQ 16
#define BK 16
#define SMEM_BYTES (2 * 256 * 16 * 4 + 256 * 128 * 4)   // 160 KB

__global__ void __launch_bounds__(256, 1)
score_kernel(const float* __restrict__ W2, const float* __restrict__ b2,
             const float* __restrict__ W3, const float* __restrict__ b3,
             float* __restrict__ scores) {
    extern __shared__ float smem[];
    float* sQP = smem;               // [256][16]
    float* sKP = smem + 256 * 16;    // [256][16]
    float* sW2 = smem + 2 * 256 * 16;// [256][128]

    const int tid = threadIdx.x;
    const int k0 = blockIdx.x * BK;
    const int q0 = blockIdx.y * BQ;
    const int b = blockIdx.z;

    // ---- tile loads (all float4) ----
    {
        float4* dq = (float4*)sQP;
        float4* dk = (float4*)sKP;
        const float* qbase = g_qp + (long)b * (HH1 * LQ);
        const float* kbase = g_kp + (long)b * (HH1 * LK);
        #pragma unroll 2
        for (int i4 = tid; i4 < 1024; i4 += 256) {
            int h = i4 >> 2, qi = (i4 & 3) << 2;
            dq[i4] = *(const float4*)(qbase + (long)h * LQ + q0 + qi);
        }
        #pragma unroll 2
        for (int i4 = tid; i4 < 1024; i4 += 256) {
            int h = i4 >> 2, ki = (i4 & 3) << 2;
            dk[i4] = *(const float4*)(kbase + (long)h * LK + k0 + ki);
        }
        const float4* w2s = (const float4*)W2;
        float4* dw = (float4*)sW2;
        #pragma unroll 4
        for (int i4 = tid; i4 < 8192; i4 += 256) dw[i4] = w2s[i4];
    }
    __syncthreads();

    const int jt = tid & 7;
    const int kt = (tid >> 3) & 3;
    const int qt = tid >> 5;
    const int rot = (jt + (jt >> 2)) & 3;   // bank-conflict-free W2 reads

    unsigned long long acc[8][8];
    #pragma unroll
    for (int p = 0; p < 8; p++)
        #pragma unroll
        for (int t = 0; t < 8; t++) acc[p][t] = 0ull;

    const float2* qp2 = (const float2*)sQP + qt;                 // +h*8
    const float4* kp4 = (const float4*)sKP + kt;                 // +h*4
    const ulonglong2* wr2 = (const ulonglong2*)sW2 + (jt << 2);  // +h*32

    #pragma unroll 2
    for (int h = 0; h < 256; h++) {
        float2 qv = qp2[h * 8];
        float4 kv = kp4[h * 4];
        float hqs[2] = {qv.x, qv.y};
        float hks[4] = {kv.x, kv.y, kv.z, kv.w};

        unsigned long long hx[8];
        #pragma unroll
        for (int qi = 0; qi < 2; qi++)
            #pragma unroll
            for (int ki = 0; ki < 4; ki++) {
                float x = hqs[qi] + hks[ki];
                x = fmaxf(x, 0.f);
                hx[qi * 4 + ki] = dup2(x);
            }

        ulonglong2 wv[4];
        #pragma unroll
        for (int t = 0; t < 4; t++) {
            int qi = (t + rot) & 3;
            wv[qi] = wr2[h * 32 + qi];
        }

        #pragma unroll
        for (int p = 0; p < 8; p++) {
            #pragma unroll
            for (int t = 0; t < 4; t++) {
                acc[p][2 * t]     = ffma2(hx[p], wv[t].x, acc[p][2 * t]);
                acc[p][2 * t + 1] = ffma2(hx[p], wv[t].y, acc[p][2 * t + 1]);
            }
        }
    }

    // ---- epilogue: relu(h2pre+b2) . W3, reduce over the 8 j-threads ----
    const int j0 = jt * 16;
    float b2v[16], w3v[16];
    #pragma unroll
    for (int jj = 0; jj < 16; jj++) {
        b2v[jj] = __ldg(b2 + j0 + jj);
        w3v[jj] = __ldg(W3 + j0 + jj);
    }

    float sc[8];
    #pragma unroll
    for (int p = 0; p < 8; p++) {
        float s = 0.f;
        #pragma unroll
        for (int t = 0; t < 8; t++) {
            float2 v = unpk(acc[p][t]);
            s = fmaf(fmaxf(v.x + b2v[2 * t], 0.f), w3v[2 * t], s);
            s = fmaf(fmaxf(v.y + b2v[2 * t + 1], 0.f), w3v[2 * t + 1], s);
        }
        sc[p] = s;
    }

    #pragma unroll
    for (int off = 1; off < 8; off <<= 1)
        #pragma unroll
        for (int p = 0; p < 8; p++)
            sc[p] += __shfl_xor_sync(0xffffffffu, sc[p], off);

    if (jt == 0) {
        const float bb3 = __ldg(b3);
        #pragma unroll
        for (int p = 0; p < 8; p++) {
            int qi = p >> 2, ki = p & 3;
            int q = q0 + qt * 2 + qi;
            int k = k0 + kt * 4 + ki;
            scores[((long)b * LQ + q) * LK + k] = sc[p] + bb3;
        }
    }
}

// ---------------------------------------------------------------------------
// Kernel 3: mask + softmax over k (in place on attn) + out = attn @ V.
// Block handles 4 q-rows; 256 threads.
// ---------------------------------------------------------------------------
__global__ void softmax_av_kernel(const float* __restrict__ value,
                                  const int* __restrict__ mask,
                                  float* __restrict__ out,
                                  float* __restrict__ attn) {
    __shared__ float srow[4][LK];
    __shared__ float red[256];
    const int b = blockIdx.y;
    const int q0 = blockIdx.x * 4;
    const int tid = threadIdx.x;

    for (int i = tid; i < 4 * LK; i += 256) {
        int r = i >> 9, k = i & (LK - 1);
        long idx = ((long)b * LQ + q0 + r) * LK + k;
        float s = attn[idx];
        if (mask[idx] == 0) s = -1e9f;
        srow[r][k] = s;
    }
    __syncthreads();

    for (int r = 0; r < 4; r++) {
        float m = -3.4e38f;
        for (int k = tid; k < LK; k += 256) m = fmaxf(m, srow[r][k]);
        red[tid] = m;
        __syncthreads();
        for (int s = 128; s > 0; s >>= 1) {
            if (tid < s) red[tid] = fmaxf(red[tid], red[tid + s]);
            __syncthreads();
        }
        float mx = red[0];
        __syncthreads();

        float sum = 0.f;
        for (int k = tid; k < LK; k += 256) {
            float e = __expf(srow[r][k] - mx);
            srow[r][k] = e;
            sum += e;
        }
        red[tid] = sum;
        __syncthreads();
        for (int s = 128; s > 0; s >>= 1) {
            if (tid < s) red[tid] += red[tid + s];
            __syncthreads();
        }
        float inv = 1.f / red[0];
        __syncthreads();

        for (int k = tid; k < LK; k += 256) {
            float a = srow[r][k] * inv;
            srow[r][k] = a;
            attn[((long)b * LQ + q0 + r) * LK + k] = a;
        }
        __syncthreads();
    }

    // out = attn @ V  (thread = one output dim d)
    const int d = tid;
    float acc[4] = {0.f, 0.f, 0.f, 0.f};
    const float* Vb = value + (long)b * LK * DD + d;
    for (int k = 0; k < LK; k++) {
        float v = Vb[(long)k * DD];
        #pragma unroll
        for (int r = 0; r < 4; r++) acc[r] = fmaf(srow[r][k], v, acc[r]);
    }
    #pragma unroll
    for (int r = 0; r < 4; r++)
        out[((long)b * LQ + q0 + r) * DD + d] = acc[r];
}

// ---------------------------------------------------------------------------
extern "C" void kernel_launch(void* const* d_in, const int* in_sizes, int n_in,
                              void* d_out, int out_size) {
    const float* query = (const float*)d_in[0];
    const float* key   = (const float*)d_in[1];
    const float* value = (const float*)d_in[2];
    const int*   mask  = (const int*)d_in[3];
    const float* W1 = (const float*)d_in[4];
    const float* b1 = (const float*)d_in[5];
    const float* W2 = (const float*)d_in[6];
    const float* b2 = (const float*)d_in[7];
    const float* W3 = (const float*)d_in[8];
    const float* b3 = (const float*)d_in[9];

    float* out  = (float*)d_out;                    // [B, LQ, D]
    float* attn = out + (long)BB * LQ * DD;         // [B, LQ, LK]

    cudaFuncSetAttribute(score_kernel,
                         cudaFuncAttributeMaxDynamicSharedMemorySize, SMEM_BYTES);

    proj_kernel<<<dim3(LQ / 8, BB, 2), 256>>>(query, key, W1, b1);
    score_kernel<<<dim3(LK / BK, LQ / BQ, BB), 256, SMEM_BYTES>>>(W2, b2, W3, b3, attn);
    softmax_av_kernel<<<dim3(LQ / 4, BB), 256>>>(value, mask, out, attn);
}

// round 3
// speedup vs baseline: 18.8174x; 18.8174x over previous
#include <cuda_runtime.h>
#include <cstdint>

#define LQ 512
#define LK 512
#define DD 256
#define HH1 256
#define HH2 128
#define BB 2

// global scratch: projections, [b][row][h] with h contiguous
__device__ float g_qp[BB * LQ * HH1];
__device__ float g_kp[BB * LK * HH1];

// ---------------------------------------------------------------------------
// Kernel 1: projections.  g_qp[b][q][h] = query@W1q + b1 ;  g_kp = key@W1k
// ---------------------------------------------------------------------------
__global__ void proj_kernel(const float* __restrict__ query,
                            const float* __restrict__ key,
                            const float* __restrict__ W1,
                            const float* __restrict__ b1) {
    const int h = threadIdx.x;            // 0..255
    const int q0 = blockIdx.x * 4;
    const int b = blockIdx.y;
    const int which = blockIdx.z;         // 0 -> query, 1 -> key

    const float* X = (which ? key : query) + ((long)b * LQ + q0) * DD;
    __shared__ float sx[4 * DD];
    for (int i = threadIdx.x; i < 4 * DD; i += 256) sx[i] = X[i];
    __syncthreads();

    float acc[4];
    const float bias = which ? 0.f : b1[h];
    #pragma unroll
    for (int r = 0; r < 4; r++) acc[r] = bias;

    const float* Wcol = W1 + (long)(which * DD) * HH1 + h;
    #pragma unroll 8
    for (int d = 0; d < DD; d++) {
        float w = Wcol[(long)d * HH1];
        #pragma unroll
        for (int r = 0; r < 4; r++) acc[r] = fmaf(sx[r * DD + d], w, acc[r]);
    }

    float* dst = (which ? g_kp : g_qp) + ((long)b * LQ + q0) * HH1 + h;
    #pragma unroll
    for (int r = 0; r < 4; r++) dst[(long)r * HH1] = acc[r];
}

// ---------------------------------------------------------------------------
// Kernel 2: fused MLP scores via mma.sync tf32 (m16n8k8).
// CTA = 16 q x 16 k = 256 pairs (M), N = 128 (j), K = 256 (h).
// 8 warps: warp tile M=64 x N=64.  A fragments built on the fly from qp/kp.
// ---------------------------------------------------------------------------
#define SQP 260        // qp/kp smem row stride (floats): bank-conflict free
#define SW2 136        // W2 smem row stride (floats):    bank-conflict free

#define OFF_W2   0                         // [256][136]
#define OFF_QP   (256 * SW2)               // 34816: [16][260]
#define OFF_KP   (OFF_QP + 16 * SQP)       // [16][260]
#define OFF_BW   (OFF_KP + 16 * SQP)       // float2[128] (b2, W3)
#define OFF_PART (OFF_BW + 256)            // float[256] cross-warp partials
#define SMEM_FLOATS (OFF_PART + 256)
#define SMEM_BYTES (SMEM_FLOATS * 4)       // 174592

__device__ __forceinline__ void mma_tf32(float* c, const float* a, const float* b) {
    asm volatile(
        "mma.sync.aligned.m16n8k8.row.col.f32.tf32.tf32.f32 "
        "{%0,%1,%2,%3}, {%4,%5,%6,%7}, {%8,%9}, {%0,%1,%2,%3};"
        : "+f"(c[0]), "+f"(c[1]), "+f"(c[2]), "+f"(c[3])
        : "r"(__float_as_uint(a[0])), "r"(__float_as_uint(a[1])),
          "r"(__float_as_uint(a[2])), "r"(__float_as_uint(a[3])),
          "r"(__float_as_uint(b[0])), "r"(__float_as_uint(b[1])));
}

__global__ void __launch_bounds__(256, 1)
score_mma_kernel(const float* __restrict__ W2, const float* __restrict__ b2,
                 const float* __restrict__ W3, const float* __restrict__ b3,
                 float* __restrict__ scores) {
    extern __shared__ float smem[];
    const int tid = threadIdx.x;
    const int k0blk = blockIdx.x * 16, q0blk = blockIdx.y * 16, b = blockIdx.z;

    // ---- cooperative staging ----
    {
        // W2 [h=256][j=128] -> smem stride 136 (float4 stores, 136%4==0)
        const float4* src = (const float4*)W2;
        float4* dst = (float4*)(smem + OFF_W2);
        #pragma unroll 8
        for (int i4 = tid; i4 < 8192; i4 += 256) {
            int row = i4 >> 5, c4 = i4 & 31;
            dst[row * (SW2 / 4) + c4] = __ldg(src + i4);
        }
        // qp/kp tiles [16][256] -> stride 260
        const float4* gq = (const float4*)(g_qp + ((long)b * LQ + q0blk) * HH1);
        const float4* gk = (const float4*)(g_kp + ((long)b * LK + k0blk) * HH1);
        float4* dq = (float4*)(smem + OFF_QP);
        float4* dk = (float4*)(smem + OFF_KP);
        #pragma unroll 2
        for (int i4 = tid; i4 < 1024; i4 += 256) {
            int row = i4 >> 6, c4 = i4 & 63;
            dq[row * (SQP / 4) + c4] = __ldg(gq + i4);
            dk[row * (SQP / 4) + c4] = __ldg(gk + i4);
        }
        if (tid < HH2)
            ((float2*)(smem + OFF_BW))[tid] = make_float2(__ldg(b2 + tid), __ldg(W3 + tid));
    }
    __syncthreads();

    const int w = tid >> 5, lane = tid & 31;
    const int mwarp = w & 3;        // M offset = mwarp*64
    const int nwarp = w >> 2;       // N offset = nwarp*64
    const int n0 = nwarp * 64;
    const int lr = lane >> 2, lc = lane & 3;

    float acc[4][8][4];
    #pragma unroll
    for (int mt = 0; mt < 4; mt++)
        #pragma unroll
        for (int nt = 0; nt < 8; nt++)
            #pragma unroll
            for (int c = 0; c < 4; c++) acc[mt][nt][c] = 0.f;

    const float* kp0 = smem + OFF_KP + lr * SQP;          // k row = lr
    const float* kp1 = smem + OFF_KP + (lr + 8) * SQP;    // k row = lr+8
    const float* qpb = smem + OFF_QP + (mwarp * 4) * SQP; // q rows mwarp*4 + mt
    const float* w2b = smem + OFF_W2 + n0 + lr;           // + (k)*SW2 + 8*nt

    #pragma unroll 1
    for (int k0 = 0; k0 < HH1; k0 += 8) {
        // kp values shared across all 4 m-tiles
        const float kv00 = kp0[k0 + lc],     kv01 = kp0[k0 + lc + 4];
        const float kv10 = kp1[k0 + lc],     kv11 = kp1[k0 + lc + 4];

        float a[4][4];
        #pragma unroll
        for (int mt = 0; mt < 4; mt++) {
            const float qv0 = qpb[mt * SQP + k0 + lc];
            const float qv1 = qpb[mt * SQP + k0 + lc + 4];
            a[mt][0] = fmaxf(qv0 + kv00, 0.f);   // (row=lr,   col=lc)
            a[mt][1] = fmaxf(qv0 + kv10, 0.f);   // (row=lr+8, col=lc)
            a[mt][2] = fmaxf(qv1 + kv01, 0.f);   // (row=lr,   col=lc+4)
            a[mt][3] = fmaxf(qv1 + kv11, 0.f);   // (row=lr+8, col=lc+4)
        }

        float bf[8][2];
        #pragma unroll
        for (int nt = 0; nt < 8; nt++) {
            bf[nt][0] = w2b[(k0 + lc) * SW2 + 8 * nt];
            bf[nt][1] = w2b[(k0 + lc + 4) * SW2 + 8 * nt];
        }

        #pragma unroll
        for (int mt = 0; mt < 4; mt++)
            #pragma unroll
            for (int nt = 0; nt < 8; nt++)
                mma_tf32(acc[mt][nt], a[mt], bf[nt]);
    }

    // ---- epilogue: score(p) = b3 + sum_j relu(D[p][j]+b2[j])*W3[j] ----
    // D layout: c0:(lr, jj) c1:(lr, jj+1) c2:(lr+8, jj) c3:(lr+8, jj+1),
    // jj = n0 + nt*8 + 2*lc
    const float2* bw = (const float2*)(smem + OFF_BW);
    float* part = smem + OFF_PART;

    float s0[4], s1[4];
    #pragma unroll
    for (int mt = 0; mt < 4; mt++) {
        float t0 = 0.f, t1 = 0.f;
        #pragma unroll
        for (int nt = 0; nt < 8; nt++) {
            const int jj = n0 + nt * 8 + 2 * lc;
            float2 c0 = bw[jj >> 1];          // (b2[jj], W3[jj])
            float2 c1 = bw[(jj >> 1) + 0];    // placeholder
            // jj is even; jj and jj+1:
            float2 e0 = bw[jj / 2 * 0 + 0];   // unused
            (void)c1; (void)e0;
            float b2a = bw[(jj)].x, w3a = bw[(jj)].y;         // wrong idx guard
            (void)b2a; (void)w3a;
            // direct indexing (bw is float2 array indexed by j):
            float2 cA = bw[jj];
            float2 cB = bw[jj + 1];
            t0 = fmaf(fmaxf(acc[mt][nt][0] + cA.x, 0.f), cA.y, t0);
            t0 = fmaf(fmaxf(acc[mt][nt][1] + cB.x, 0.f), cB.y, t0);
            t1 = fmaf(fmaxf(acc[mt][nt][2] + cA.x, 0.f), cA.y, t1);
            t1 = fmaf(fmaxf(acc[mt][nt][3] + cB.x, 0.f), cB.y, t1);
        }
        s0[mt] = t0; s1[mt] = t1;
    }
    // reduce over the 4 lanes of each quad (same lr)
    #pragma unroll
    for (int off = 1; off < 4; off <<= 1)
        #pragma unroll
        for (int mt = 0; mt < 4; mt++) {
            s0[mt] += __shfl_xor_sync(0xffffffffu, s0[mt], off);
            s1[mt] += __shfl_xor_sync(0xffffffffu, s1[mt], off);
        }

    if (nwarp == 0 && lc == 0) {
        #pragma unroll
        for (int mt = 0; mt < 4; mt++) {
            part[mwarp * 64 + mt * 16 + lr]     = s0[mt];
            part[mwarp * 64 + mt * 16 + lr + 8] = s1[mt];
        }
    }
    __syncthreads();
    if (nwarp == 1 && lc == 0) {
        const float bb3 = __ldg(b3);
        #pragma unroll
        for (int mt = 0; mt < 4; mt++) {
            int p0 = mwarp * 64 + mt * 16 + lr;
            int p1 = p0 + 8;
            float f0 = s0[mt] + part[p0] + bb3;
            float f1 = s1[mt] + part[p1] + bb3;
            int q = q0blk + (p0 >> 4);
            scores[((long)b * LQ + q) * LK + k0blk + (p0 & 15)] = f0;
            scores[((long)b * LQ + q) * LK + k0blk + (p1 & 15)] = f1;
        }
    }
}

// ---------------------------------------------------------------------------
// Kernel 3: mask + softmax over k (in place on attn) + out = attn @ V.
// ---------------------------------------------------------------------------
__global__ void softmax_av_kernel(const float* __restrict__ value,
                                  const int* __restrict__ mask,
                                  float* __restrict__ out,
                                  float* __restrict__ attn) {
    __shared__ float srow[4][LK];
    __shared__ float red[256];
    const int b = blockIdx.y;
    const int q0 = blockIdx.x * 4;
    const int tid = threadIdx.x;

    for (int i = tid; i < 4 * LK; i += 256) {
        int r = i >> 9, k = i & (LK - 1);
        long idx = ((long)b * LQ + q0 + r) * LK + k;
        float s = attn[idx];
        if (mask[idx] == 0) s = -1e9f;
        srow[r][k] = s;
    }
    __syncthreads();

    for (int r = 0; r < 4; r++) {
        float m = -3.4e38f;
        for (int k = tid; k < LK; k += 256) m = fmaxf(m, srow[r][k]);
        red[tid] = m;
        __syncthreads();
        for (int s = 128; s > 0; s >>= 1) {
            if (tid < s) red[tid] = fmaxf(red[tid], red[tid + s]);
            __syncthreads();
        }
        float mx = red[0];
        __syncthreads();

        float sum = 0.f;
        for (int k = tid; k < LK; k += 256) {
            float e = __expf(srow[r][k] - mx);
            srow[r][k] = e;
            sum += e;
        }
        red[tid] = sum;
        __syncthreads();
        for (int s = 128; s > 0; s >>= 1) {
            if (tid < s) red[tid] += red[tid + s];
            __syncthreads();
        }
        float inv = 1.f / red[0];
        __syncthreads();

        for (int k = tid; k < LK; k += 256) {
            float a = srow[r][k] * inv;
            srow[r][k] = a;
            attn[((long)b * LQ + q0 + r) * LK + k] = a;
        }
        __syncthreads();
    }

    // out = attn @ V
    const int d = tid;
    float acc[4] = {0.f, 0.f, 0.f, 0.f};
    const float* Vb = value + (long)b * LK * DD + d;
    #pragma unroll 4
    for (int k = 0; k < LK; k++) {
        float v = Vb[(long)k * DD];
        #pragma unroll
        for (int r = 0; r < 4; r++) acc[r] = fmaf(srow[r][k], v, acc[r]);
    }
    #pragma unroll
    for (int r = 0; r < 4; r++)
        out[((long)b * LQ + q0 + r) * DD + d] = acc[r];
}

// ---------------------------------------------------------------------------
extern "C" void kernel_launch(void* const* d_in, const int* in_sizes, int n_in,
                              void* d_out, int out_size) {
    const float* query = (const float*)d_in[0];
    const float* key   = (const float*)d_in[1];
    const float* value = (const float*)d_in[2];
    const int*   mask  = (const int*)d_in[3];
    const float* W1 = (const float*)d_in[4];
    const float* b1 = (const float*)d_in[5];
    const float* W2 = (const float*)d_in[6];
    const float* b2 = (const float*)d_in[7];
    const float* W3 = (const float*)d_in[8];
    const float* b3 = (const float*)d_in[9];

    float* out  = (float*)d_out;                 // [B, LQ, D]
    float* attn = out + (long)BB * LQ * DD;      // [B, LQ, LK]

    cudaFuncSetAttribute(score_mma_kernel,
                         cudaFuncAttributeMaxDynamicSharedMemorySize, SMEM_BYTES);

    proj_kernel<<<dim3(LQ / 4, BB, 2), 256>>>(query, key, W1, b1);
    score_mma_kernel<<<dim3(LK / 16, LQ / 16, BB), 256, SMEM_BYTES>>>(W2, b2, W3, b3, attn);
    softmax_av_kernel<<<dim3(LQ / 4, BB), 256>>>(value, mask, out, attn);
}

// round 4
// speedup vs baseline: 20.0586x; 1.0660x over previous
#include <cuda_runtime.h>
#include <cstdint>

#define LQ 512
#define LK 512
#define DD 256
#define HH1 256
#define HH2 128
#define BB 2

// global scratch: projections, [b][row][h] with h contiguous
__device__ float g_qp[BB * LQ * HH1];
__device__ float g_kp[BB * LK * HH1];

// ---------------------------------------------------------------------------
// Kernel 1: projections with smem-tiled W1.
// Block: 16 rows, 256 threads (thread = output h). W1 streamed in 64-d chunks.
// ---------------------------------------------------------------------------
#define PROJ_SMEM ((16 * 256 + 64 * 256) * 4)   // 80 KB

__global__ void __launch_bounds__(256, 1)
proj_kernel(const float* __restrict__ query,
            const float* __restrict__ key,
            const float* __restrict__ W1,
            const float* __restrict__ b1) {
    extern __shared__ float psm[];
    float* sx = psm;              // [16][256]
    float* sw = psm + 16 * 256;   // [64][256]

    const int h = threadIdx.x;
    const int r0 = blockIdx.x * 16;
    const int b = blockIdx.y;
    const int which = blockIdx.z;       // 0 -> query, 1 -> key

    {
        const float4* X4 = (const float4*)((which ? key : query) + ((long)b * LQ + r0) * DD);
        float4* sx4 = (float4*)sx;
        #pragma unroll
        for (int i = h; i < 1024; i += 256) sx4[i] = __ldg(X4 + i);
    }

    float acc[16];
    const float bias = which ? 0.f : __ldg(b1 + h);
    #pragma unroll
    for (int r = 0; r < 16; r++) acc[r] = bias;

    #pragma unroll 1
    for (int dc = 0; dc < 4; dc++) {
        __syncthreads();
        {
            const float4* w4 = (const float4*)(W1 + (long)(which * DD + dc * 64) * HH1);
            float4* sw4 = (float4*)sw;
            #pragma unroll
            for (int i = h; i < 4096; i += 256) sw4[i] = __ldg(w4 + i);
        }
        __syncthreads();

        #pragma unroll
        for (int d4 = 0; d4 < 16; d4++) {
            const int d = dc * 64 + d4 * 4;
            const float w0 = sw[(d4 * 4 + 0) * 256 + h];
            const float w1 = sw[(d4 * 4 + 1) * 256 + h];
            const float w2 = sw[(d4 * 4 + 2) * 256 + h];
            const float w3 = sw[(d4 * 4 + 3) * 256 + h];
            #pragma unroll
            for (int r = 0; r < 16; r++) {
                float4 xv = *(const float4*)(sx + r * 256 + d);
                acc[r] = fmaf(xv.x, w0, acc[r]);
                acc[r] = fmaf(xv.y, w1, acc[r]);
                acc[r] = fmaf(xv.z, w2, acc[r]);
                acc[r] = fmaf(xv.w, w3, acc[r]);
            }
        }
    }

    float* dst = (which ? g_kp : g_qp) + ((long)b * LQ + r0) * HH1 + h;
    #pragma unroll
    for (int r = 0; r < 16; r++) dst[(long)r * HH1] = acc[r];
}

// ---------------------------------------------------------------------------
// Kernel 2: fused MLP scores via mma.sync tf32 (m16n8k8).
// CTA = 16 q x 16 k = 256 pairs (M), N = 128 (j), K = 256 (h).
// 8 warps: warp tile M=64 x N=64.  A fragments built on the fly from qp/kp.
// Register double-buffered fragment prefetch hides LDS latency under MMAs.
// ---------------------------------------------------------------------------
#define SQP 260        // qp/kp smem row stride (floats): bank-conflict free
#define SW2 136        // W2 smem row stride (floats):    bank-conflict free

#define OFF_W2   0                         // [256][136]
#define OFF_QP   (256 * SW2)               // [16][260]
#define OFF_KP   (OFF_QP + 16 * SQP)       // [16][260]
#define OFF_BW   (OFF_KP + 16 * SQP)       // float2[128] (b2, W3)
#define OFF_PART (OFF_BW + 256)            // float[256] cross-warp partials
#define SMEM_FLOATS (OFF_PART + 256)
#define SMEM_BYTES (SMEM_FLOATS * 4)       // 174592

__device__ __forceinline__ void mma_tf32(float* c, const float* a, const float* b) {
    asm volatile(
        "mma.sync.aligned.m16n8k8.row.col.f32.tf32.tf32.f32 "
        "{%0,%1,%2,%3}, {%4,%5,%6,%7}, {%8,%9}, {%0,%1,%2,%3};"
        : "+f"(c[0]), "+f"(c[1]), "+f"(c[2]), "+f"(c[3])
        : "r"(__float_as_uint(a[0])), "r"(__float_as_uint(a[1])),
          "r"(__float_as_uint(a[2])), "r"(__float_as_uint(a[3])),
          "r"(__float_as_uint(b[0])), "r"(__float_as_uint(b[1])));
}

__global__ void __launch_bounds__(256, 1)
score_mma_kernel(const float* __restrict__ W2, const float* __restrict__ b2,
                 const float* __restrict__ W3, const float* __restrict__ b3,
                 float* __restrict__ scores) {
    extern __shared__ float smem[];
    const int tid = threadIdx.x;
    const int k0blk = blockIdx.x * 16, q0blk = blockIdx.y * 16, b = blockIdx.z;

    // ---- cooperative staging ----
    {
        const float4* src = (const float4*)W2;
        float4* dst = (float4*)(smem + OFF_W2);
        #pragma unroll 8
        for (int i4 = tid; i4 < 8192; i4 += 256) {
            int row = i4 >> 5, c4 = i4 & 31;
            dst[row * (SW2 / 4) + c4] = __ldg(src + i4);
        }
        const float4* gq = (const float4*)(g_qp + ((long)b * LQ + q0blk) * HH1);
        const float4* gk = (const float4*)(g_kp + ((long)b * LK + k0blk) * HH1);
        float4* dq = (float4*)(smem + OFF_QP);
        float4* dk = (float4*)(smem + OFF_KP);
        #pragma unroll 2
        for (int i4 = tid; i4 < 1024; i4 += 256) {
            int row = i4 >> 6, c4 = i4 & 63;
            dq[row * (SQP / 4) + c4] = __ldg(gq + i4);
            dk[row * (SQP / 4) + c4] = __ldg(gk + i4);
        }
        if (tid < HH2)
            ((float2*)(smem + OFF_BW))[tid] = make_float2(__ldg(b2 + tid), __ldg(W3 + tid));
    }
    __syncthreads();

    const int w = tid >> 5, lane = tid & 31;
    const int mwarp = w & 3;        // M offset = mwarp*64
    const int nwarp = w >> 2;       // N offset = nwarp*64
    const int n0 = nwarp * 64;
    const int lr = lane >> 2, lc = lane & 3;

    float acc[4][8][4];
    #pragma unroll
    for (int mt = 0; mt < 4; mt++)
        #pragma unroll
        for (int nt = 0; nt < 8; nt++)
            #pragma unroll
            for (int c = 0; c < 4; c++) acc[mt][nt][c] = 0.f;

    const float* kp0 = smem + OFF_KP + lr * SQP;          // k row = lr
    const float* kp1 = smem + OFF_KP + (lr + 8) * SQP;    // k row = lr+8
    const float* qpb = smem + OFF_QP + (mwarp * 4) * SQP; // q rows mwarp*4 + mt
    const float* w2b = smem + OFF_W2 + n0 + lr;           // + (k)*SW2 + 8*nt

    // fragment double buffers
    float kv[2][4], qv[2][4][2], bf[2][8][2];

#define LOAD_FRAG(B, K0) do { \
        kv[B][0] = kp0[(K0) + lc];     kv[B][1] = kp0[(K0) + lc + 4]; \
        kv[B][2] = kp1[(K0) + lc];     kv[B][3] = kp1[(K0) + lc + 4]; \
        _Pragma("unroll") \
        for (int mt = 0; mt < 4; mt++) { \
            qv[B][mt][0] = qpb[mt * SQP + (K0) + lc]; \
            qv[B][mt][1] = qpb[mt * SQP + (K0) + lc + 4]; \
        } \
        _Pragma("unroll") \
        for (int nt = 0; nt < 8; nt++) { \
            bf[B][nt][0] = w2b[((K0) + lc) * SW2 + 8 * nt]; \
            bf[B][nt][1] = w2b[((K0) + lc + 4) * SW2 + 8 * nt]; \
        } \
    } while (0)

    LOAD_FRAG(0, 0);

    #pragma unroll 2
    for (int k0 = 0; k0 < HH1; k0 += 8) {
        const int cur = (k0 >> 3) & 1;
        if (k0 + 8 < HH1) LOAD_FRAG(cur ^ 1, k0 + 8);

        float a[4][4];
        #pragma unroll
        for (int mt = 0; mt < 4; mt++) {
            a[mt][0] = fmaxf(qv[cur][mt][0] + kv[cur][0], 0.f);  // (lr,   lc)
            a[mt][1] = fmaxf(qv[cur][mt][0] + kv[cur][2], 0.f);  // (lr+8, lc)
            a[mt][2] = fmaxf(qv[cur][mt][1] + kv[cur][1], 0.f);  // (lr,   lc+4)
            a[mt][3] = fmaxf(qv[cur][mt][1] + kv[cur][3], 0.f);  // (lr+8, lc+4)
        }

        #pragma unroll
        for (int mt = 0; mt < 4; mt++)
            #pragma unroll
            for (int nt = 0; nt < 8; nt++)
                mma_tf32(acc[mt][nt], a[mt], bf[cur][nt]);
    }
#undef LOAD_FRAG

    // ---- epilogue: score(p) = b3 + sum_j relu(D[p][j]+b2[j])*W3[j] ----
    // D frag: c0:(lr, jj) c1:(lr, jj+1) c2:(lr+8, jj) c3:(lr+8, jj+1),
    // jj = n0 + nt*8 + 2*lc
    const float2* bw = (const float2*)(smem + OFF_BW);
    float* part = smem + OFF_PART;

    float s0[4], s1[4];
    #pragma unroll
    for (int mt = 0; mt < 4; mt++) {
        float t0 = 0.f, t1 = 0.f;
        #pragma unroll
        for (int nt = 0; nt < 8; nt++) {
            const int jj = n0 + nt * 8 + 2 * lc;
            float2 cA = bw[jj];
            float2 cB = bw[jj + 1];
            t0 = fmaf(fmaxf(acc[mt][nt][0] + cA.x, 0.f), cA.y, t0);
            t0 = fmaf(fmaxf(acc[mt][nt][1] + cB.x, 0.f), cB.y, t0);
            t1 = fmaf(fmaxf(acc[mt][nt][2] + cA.x, 0.f), cA.y, t1);
            t1 = fmaf(fmaxf(acc[mt][nt][3] + cB.x, 0.f), cB.y, t1);
        }
        s0[mt] = t0; s1[mt] = t1;
    }
    #pragma unroll
    for (int off = 1; off < 4; off <<= 1)
        #pragma unroll
        for (int mt = 0; mt < 4; mt++) {
            s0[mt] += __shfl_xor_sync(0xffffffffu, s0[mt], off);
            s1[mt] += __shfl_xor_sync(0xffffffffu, s1[mt], off);
        }

    if (nwarp == 0 && lc == 0) {
        #pragma unroll
        for (int mt = 0; mt < 4; mt++) {
            part[mwarp * 64 + mt * 16 + lr]     = s0[mt];
            part[mwarp * 64 + mt * 16 + lr + 8] = s1[mt];
        }
    }
    __syncthreads();
    if (nwarp == 1 && lc == 0) {
        const float bb3 = __ldg(b3);
        #pragma unroll
        for (int mt = 0; mt < 4; mt++) {
            int p0 = mwarp * 64 + mt * 16 + lr;
            int p1 = p0 + 8;
            float f0 = s0[mt] + part[p0] + bb3;
            float f1 = s1[mt] + part[p1] + bb3;
            int q = q0blk + (p0 >> 4);
            scores[((long)b * LQ + q) * LK + k0blk + (p0 & 15)] = f0;
            scores[((long)b * LQ + q) * LK + k0blk + (p1 & 15)] = f1;
        }
    }
}

// ---------------------------------------------------------------------------
// Kernel 3: mask + softmax over k (warp-per-row, 8 rows/block) + out = attn@V.
// ---------------------------------------------------------------------------
__global__ void __launch_bounds__(256, 1)
softmax_av_kernel(const float* __restrict__ value,
                  const int* __restrict__ mask,
                  float* __restrict__ out,
                  float* __restrict__ attn) {
    __shared__ float srow[8][LK];
    const int b = blockIdx.y;
    const int q0 = blockIdx.x * 8;
    const int tid = threadIdx.x;
    const int w = tid >> 5, lane = tid & 31;

    // warp w owns row w: load + mask + max + exp-sum + normalize + write attn
    {
        const int r = w;
        const long rowbase = ((long)b * LQ + q0 + r) * LK;
        float vals[16];
        float mx = -3.4e38f;
        #pragma unroll
        for (int i = 0; i < 16; i++) {
            int k = lane + i * 32;
            float s = attn[rowbase + k];
            if (mask[rowbase + k] == 0) s = -1e9f;
            vals[i] = s;
            mx = fmaxf(mx, s);
        }
        #pragma unroll
        for (int off = 16; off > 0; off >>= 1)
            mx = fmaxf(mx, __shfl_xor_sync(0xffffffffu, mx, off));

        float sum = 0.f;
        #pragma unroll
        for (int i = 0; i < 16; i++) {
            vals[i] = __expf(vals[i] - mx);
            sum += vals[i];
        }
        #pragma unroll
        for (int off = 16; off > 0; off >>= 1)
            sum += __shfl_xor_sync(0xffffffffu, sum, off);
        const float inv = 1.f / sum;

        #pragma unroll
        for (int i = 0; i < 16; i++) {
            int k = lane + i * 32;
            float a = vals[i] * inv;
            srow[r][k] = a;
            attn[rowbase + k] = a;
        }
    }
    __syncthreads();

    // out = attn @ V   (thread = one output dim d, 8 rows accumulated)
    const int d = tid;
    float acc[8] = {0.f, 0.f, 0.f, 0.f, 0.f, 0.f, 0.f, 0.f};
    const float* Vb = value + (long)b * LK * DD + d;
    #pragma unroll 4
    for (int k = 0; k < LK; k++) {
        float v = __ldg(Vb + (long)k * DD);
        #pragma unroll
        for (int r = 0; r < 8; r++) acc[r] = fmaf(srow[r][k], v, acc[r]);
    }
    #pragma unroll
    for (int r = 0; r < 8; r++)
        out[((long)b * LQ + q0 + r) * DD + d] = acc[r];
}

// ---------------------------------------------------------------------------
extern "C" void kernel_launch(void* const* d_in, const int* in_sizes, int n_in,
                              void* d_out, int out_size) {
    const float* query = (const float*)d_in[0];
    const float* key   = (const float*)d_in[1];
    const float* value = (const float*)d_in[2];
    const int*   mask  = (const int*)d_in[3];
    const float* W1 = (const float*)d_in[4];
    const float* b1 = (const float*)d_in[5];
    const float* W2 = (const float*)d_in[6];
    const float* b2 = (const float*)d_in[7];
    const float* W3 = (const float*)d_in[8];
    const float* b3 = (const float*)d_in[9];

    float* out  = (float*)d_out;                 // [B, LQ, D]
    float* attn = out + (long)BB * LQ * DD;      // [B, LQ, LK]

    cudaFuncSetAttribute(proj_kernel,
                         cudaFuncAttributeMaxDynamicSharedMemorySize, PROJ_SMEM);
    cudaFuncSetAttribute(score_mma_kernel,
                         cudaFuncAttributeMaxDynamicSharedMemorySize, SMEM_BYTES);

    proj_kernel<<<dim3(LQ / 16, BB, 2), 256, PROJ_SMEM>>>(query, key, W1, b1);
    score_mma_kernel<<<dim3(LK / 16, LQ / 16, BB), 256, SMEM_BYTES>>>(W2, b2, W3, b3, attn);
    softmax_av_kernel<<<dim3(LQ / 8, BB), 256>>>(value, mask, out, attn);
}